// round 9
// baseline (speedup 1.0000x reference)
#include <cuda_runtime.h>
#include <cuda_bf16.h>
#include <math_constants.h>
#include <cstdint>

#define NN 512
#define BB 4
#define HH 4
#define FF 64
#define NCHT 8      // T-partial chunks = 8 m-tiles of 64 rows

// ---------------- scratch (device globals; no allocation) ----------------
__device__ float g_d[NN];
__device__ float g_c[NN];
__device__ float g_cpart[128 * NN];
__device__ float g_nor[NN * NN];
__device__ __nv_bfloat16 g_qh[BB * HH * NN * FF];  // q hi (pre-scaled 1/8)
__device__ __nv_bfloat16 g_ql[BB * HH * NN * FF];  // q lo
__device__ __nv_bfloat16 g_kh[BB * HH * NN * FF];  // k hi
__device__ __nv_bfloat16 g_kl[BB * HH * NN * FF];  // k lo
__device__ float g_Tpart[NCHT * BB * HH * NN];
__device__ float g_T[BB * HH * NN];

// ---------------- f32x2 helpers ----------------
__device__ __forceinline__ unsigned long long f2pack(float a, float b) {
    unsigned long long r;
    asm("mov.b64 %0,{%1,%2};" : "=l"(r) : "f"(a), "f"(b));
    return r;
}
__device__ __forceinline__ void f2fma(unsigned long long& d, unsigned long long a,
                                      unsigned long long b) {
    asm("fma.rn.f32x2 %0,%1,%2,%0;" : "+l"(d) : "l"(a), "l"(b));
}
__device__ __forceinline__ void f2unpack(unsigned long long v, float& a, float& b) {
    asm("mov.b64 {%0,%1},%2;" : "=f"(a), "=f"(b) : "l"(v));
}

// ---------------- HMMA m16n8k16 bf16 -> f32 ----------------
__device__ __forceinline__ void mma16816(float d[4], const uint32_t a[4],
                                         const uint32_t b[2]) {
    asm volatile(
        "mma.sync.aligned.m16n8k16.row.col.f32.bf16.bf16.f32 "
        "{%0,%1,%2,%3}, {%4,%5,%6,%7}, {%8,%9}, {%0,%1,%2,%3};"
        : "+f"(d[0]), "+f"(d[1]), "+f"(d[2]), "+f"(d[3])
        : "r"(a[0]), "r"(a[1]), "r"(a[2]), "r"(a[3]), "r"(b[0]), "r"(b[1]));
}

__device__ __forceinline__ uint32_t smem_u32(const void* p) {
    uint32_t r;
    asm("{ .reg .u64 t; cvta.to.shared.u64 t, %1; cvt.u32.u64 %0, t; }"
        : "=r"(r) : "l"(p));
    return r;
}
__device__ __forceinline__ void ldsm4(uint32_t r[4], uint32_t addr) {
    asm volatile("ldmatrix.sync.aligned.m8n8.x4.shared.b16 {%0,%1,%2,%3}, [%4];"
                 : "=r"(r[0]), "=r"(r[1]), "=r"(r[2]), "=r"(r[3]) : "r"(addr));
}

__device__ __forceinline__ float blockReduceSum256(float v, float* red) {
    #pragma unroll
    for (int o = 16; o; o >>= 1) v += __shfl_xor_sync(0xffffffffu, v, o);
    int wid = threadIdx.x >> 5, lane = threadIdx.x & 31;
    if (lane == 0) red[wid] = v;
    __syncthreads();
    float r = (threadIdx.x < 8) ? red[threadIdx.x] : 0.f;
    if (wid == 0) {
        #pragma unroll
        for (int o = 4; o; o >>= 1) r += __shfl_xor_sync(0xffffffffu, r, o);
    }
    return r;
}

// ---------------- K1a: degrees ----------------
__global__ void k_deg(const float* __restrict__ adj) {
    __shared__ float red[8];
    int i = blockIdx.x;
    float s = 0.f;
    for (int j = threadIdx.x; j < NN; j += 256) s += adj[i * NN + j];
    s = blockReduceSum256(s, red);
    if (threadIdx.x == 0) g_d[i] = rsqrtf(s + 1.0f);
}

// ---------------- K1b: normalized adjacency + col-sum partials ----------
__global__ __launch_bounds__(512) void k_nor(const float* __restrict__ adj) {
    const int bk = blockIdx.x;
    const int j = threadIdx.x;
    const float dj = g_d[j];
    float s = 0.f;
    #pragma unroll
    for (int r = 0; r < 4; r++) {
        int i = bk * 4 + r;
        float a = adj[i * NN + j] + (i == j ? 1.0f : 0.0f);
        float v = g_d[i] * dj * a;
        g_nor[i * NN + j] = v;
        s += v;
    }
    g_cpart[bk * NN + j] = s;
}

// ---------------- K2: q/k projections -> bf16 hi/lo ---------------------
__global__ __launch_bounds__(256) void k_proj(const float* __restrict__ x,
                                              const float* __restrict__ Wq,
                                              const float* __restrict__ bq,
                                              const float* __restrict__ Wk,
                                              const float* __restrict__ bk) {
    const int by = blockIdx.y;
    const bool isK = by >= 4;
    const float* W = isK ? Wk : Wq;
    const float* bias = isK ? bk : bq;
    const int h = isK ? by - 4 : by;
    const int c0 = h * 64;
    const int rowBase = blockIdx.x * 64;
    const int b = rowBase >> 9;
    const int bh = b * HH + h;
    const int nb = rowBase & 511;

    __shared__ float xs[64][65];
    __shared__ float ws[64][64];

    const int t = threadIdx.x;
    const int tx = t & 15, ty = t >> 4;

    #pragma unroll
    for (int i = 0; i < 4; i++) {
        int lin4 = t + i * 256;
        int r = lin4 >> 4, c4 = (lin4 & 15) * 4;
        float4 v = *(const float4*)(x + rowBase * 64 + lin4 * 4);
        xs[r][c4] = v.x; xs[r][c4 + 1] = v.y; xs[r][c4 + 2] = v.z; xs[r][c4 + 3] = v.w;
        *(float4*)&ws[r][c4] = *(const float4*)(W + r * 256 + c0 + c4);
    }
    __syncthreads();

    float acc[4][4];
    #pragma unroll
    for (int i = 0; i < 4; i++)
        #pragma unroll
        for (int jj = 0; jj < 4; jj++) acc[i][jj] = 0.f;

    #pragma unroll 8
    for (int k = 0; k < 64; k++) {
        float a0 = xs[4 * ty + 0][k];
        float a1 = xs[4 * ty + 1][k];
        float a2 = xs[4 * ty + 2][k];
        float a3 = xs[4 * ty + 3][k];
        float4 bv = *(float4*)&ws[k][4 * tx];
        acc[0][0] += a0 * bv.x; acc[0][1] += a0 * bv.y; acc[0][2] += a0 * bv.z; acc[0][3] += a0 * bv.w;
        acc[1][0] += a1 * bv.x; acc[1][1] += a1 * bv.y; acc[1][2] += a1 * bv.z; acc[1][3] += a1 * bv.w;
        acc[2][0] += a2 * bv.x; acc[2][1] += a2 * bv.y; acc[2][2] += a2 * bv.z; acc[2][3] += a2 * bv.w;
        acc[3][0] += a3 * bv.x; acc[3][1] += a3 * bv.y; acc[3][2] += a3 * bv.z; acc[3][3] += a3 * bv.w;
    }

    float4 bb = *(const float4*)&bias[c0 + 4 * tx];
    const float sc = isK ? 1.0f : 0.125f;   // fold 1/sqrt(F) into q
    __nv_bfloat16* dh = isK ? g_kh : g_qh;
    __nv_bfloat16* dl = isK ? g_kl : g_ql;
    #pragma unroll
    for (int rr = 0; rr < 4; rr++) {
        int n = nb + 4 * ty + rr;
        size_t o = (size_t)(bh * NN + n) * FF + 4 * tx;
        float v0 = (acc[rr][0] + bb.x) * sc;
        float v1 = (acc[rr][1] + bb.y) * sc;
        float v2 = (acc[rr][2] + bb.z) * sc;
        float v3 = (acc[rr][3] + bb.w) * sc;
        __nv_bfloat16 h0 = __float2bfloat16(v0), h1 = __float2bfloat16(v1);
        __nv_bfloat16 h2 = __float2bfloat16(v2), h3 = __float2bfloat16(v3);
        *(__nv_bfloat162*)&dh[o]     = __halves2bfloat162(h0, h1);
        *(__nv_bfloat162*)&dh[o + 2] = __halves2bfloat162(h2, h3);
        *(__nv_bfloat162*)&dl[o] = __halves2bfloat162(
            __float2bfloat16(v0 - __bfloat162float(h0)),
            __float2bfloat16(v1 - __bfloat162float(h1)));
        *(__nv_bfloat162*)&dl[o + 2] = __halves2bfloat162(
            __float2bfloat16(v2 - __bfloat162float(h2)),
            __float2bfloat16(v3 - __bfloat162float(h3)));
    }
}

// ---------------- K3: HMMA scores (ldmatrix) + softmax + noradj reduce ---
// grid (8 mtiles, H, B) = 128 blocks, 512 threads (16 warps).
#define QS 4608        // 64*72 elems
#define KS 18432       // 256*72 elems
#define ATTN_DSM 225280
__global__ __launch_bounds__(512, 1) void k_attn_mma() {
    extern __shared__ __align__(16) char dsm[];
    __nv_bfloat16* qh_s = (__nv_bfloat16*)dsm;
    __nv_bfloat16* ql_s = qh_s + QS;
    __nv_bfloat16* kh_s = qh_s + 2 * QS;
    __nv_bfloat16* kl_s = kh_s + KS;
    float* expb = (float*)(dsm + 92160);   // 64 x 520 fp32

    __shared__ float rsum[4][64];
    __shared__ float rinv[64];

    const int mtile = blockIdx.x, h = blockIdx.y, b = blockIdx.z;
    const int bh = b * HH + h;
    const int iBase = mtile * 64;
    const int tid = threadIdx.x;
    const int w = tid >> 5, lane = tid & 31;
    const int mrow = (w >> 2) * 16;     // warp's 16-row strip
    const int cq = w & 3;               // 64-col strip within a 256-col half
    const int r = lane >> 2, c = lane & 3;

    const uint32_t qh_b = smem_u32(qh_s), ql_b = smem_u32(ql_s);
    const uint32_t kh_b = smem_u32(kh_s), kl_b = smem_u32(kl_s);

    // --- load q (hi/lo) into smem: 512 uint4 each ---
    {
        const uint4* sh = (const uint4*)(g_qh + (size_t)(bh * NN + iBase) * FF);
        const uint4* sl = (const uint4*)(g_ql + (size_t)(bh * NN + iBase) * FF);
        int row = tid >> 3, c8 = tid & 7;
        *(uint4*)&qh_s[row * 72 + c8 * 8] = sh[tid];
        *(uint4*)&ql_s[row * 72 + c8 * 8] = sl[tid];
    }

    uint32_t qhA[4][4], qlA[4][4];
    float rs0 = 0.f, rs1 = 0.f;

    // ldmatrix lane addressing precompute
    const int arow = mrow + (lane & 7) + ((lane >> 3) & 1) * 8;   // A quads
    const uint32_t aoff = (uint32_t)(arow * 72 + (lane >> 4) * 8) * 2;
    const int brow0 = cq * 64 + (lane & 7);
    const uint32_t boff_lane = (uint32_t)((lane >> 3) * 8) * 2;

    for (int half = 0; half < 2; half++) {
        __syncthreads();   // prev-half k reads done (and q stores visible)
        // --- load k half (hi/lo): 2048 uint4 each ---
        {
            const uint4* sh = (const uint4*)(g_kh + (size_t)(bh * NN + half * 256) * FF);
            const uint4* sl = (const uint4*)(g_kl + (size_t)(bh * NN + half * 256) * FF);
            #pragma unroll
            for (int i = 0; i < 4; i++) {
                int idx = tid + i * 512;      // 0..2047
                int row = idx >> 3, c8 = idx & 7;
                *(uint4*)&kh_s[row * 72 + c8 * 8] = sh[idx];
                *(uint4*)&kl_s[row * 72 + c8 * 8] = sl[idx];
            }
        }
        __syncthreads();

        if (half == 0) {
            #pragma unroll
            for (int kt = 0; kt < 4; kt++) {
                ldsm4(qhA[kt], qh_b + aoff + kt * 32);
                ldsm4(qlA[kt], ql_b + aoff + kt * 32);
            }
        }

        #pragma unroll 2
        for (int nt = 0; nt < 8; nt++) {
            const uint32_t bb = (uint32_t)((brow0 + nt * 8) * 144) + boff_lane;
            uint32_t khx[8], klx[8];
            ldsm4(khx, kh_b + bb);
            ldsm4(khx + 4, kh_b + bb + 64);
            ldsm4(klx, kl_b + bb);
            ldsm4(klx + 4, kl_b + bb + 64);

            float d0[4] = {0.f, 0.f, 0.f, 0.f};
            float d1[4] = {0.f, 0.f, 0.f, 0.f};
            float d2[4] = {0.f, 0.f, 0.f, 0.f};
            #pragma unroll
            for (int kt = 0; kt < 4; kt++) {
                mma16816(d0, qhA[kt], khx + 2 * kt);
                mma16816(d1, qhA[kt], klx + 2 * kt);
                mma16816(d2, qlA[kt], khx + 2 * kt);
            }
            float e0 = __expf(d0[0] + d1[0] + d2[0]);
            float e1 = __expf(d0[1] + d1[1] + d2[1]);
            float e2 = __expf(d0[2] + d1[2] + d2[2]);
            float e3 = __expf(d0[3] + d1[3] + d2[3]);
            rs0 += e0 + e1;
            rs1 += e2 + e3;
            int gcol = half * 256 + cq * 64 + nt * 8 + 2 * c;
            *(float2*)&expb[(mrow + r) * 520 + gcol]     = make_float2(e0, e1);
            *(float2*)&expb[(mrow + r + 8) * 520 + gcol] = make_float2(e2, e3);
        }
    }

    // --- rowsums: reduce over quad, combine 4 col strips ---
    rs0 += __shfl_xor_sync(0xffffffffu, rs0, 1);
    rs0 += __shfl_xor_sync(0xffffffffu, rs0, 2);
    rs1 += __shfl_xor_sync(0xffffffffu, rs1, 1);
    rs1 += __shfl_xor_sync(0xffffffffu, rs1, 2);
    if ((lane & 3) == 0) {
        rsum[cq][mrow + r] = rs0;
        rsum[cq][mrow + r + 8] = rs1;
    }
    __syncthreads();
    if (tid < 64)
        rinv[tid] = 1.0f / (rsum[0][tid] + rsum[1][tid] + rsum[2][tid] + rsum[3][tid]);
    __syncthreads();

    // --- T partial: one column per thread, dual chains for MLP -----------
    {
        const float* np = g_nor + (size_t)iBase * NN;
        float a0 = 0.f, a1 = 0.f;
        #pragma unroll 8
        for (int i = 0; i < 64; i += 2) {
            a0 += np[i * NN + tid]       * (expb[i * 520 + tid] * rinv[i]);
            a1 += np[(i + 1) * NN + tid] * (expb[(i + 1) * 520 + tid] * rinv[i + 1]);
        }
        g_Tpart[mtile * (BB * HH * NN) + bh * NN + tid] = a0 + a1;
    }
}

// ---------------- K3b: reduce T partials + column sums c ----------------
__global__ void k_red() {
    if (blockIdx.x < 16) {
        int v = blockIdx.x * 512 + threadIdx.x;
        float s = 0.f;
        #pragma unroll
        for (int ch = 0; ch < NCHT; ch++) s += g_Tpart[ch * (BB * HH * NN) + v];
        g_T[v] = s;
    } else {
        int j = threadIdx.x;
        float s = 0.f;
        #pragma unroll
        for (int p = 0; p < 128; p++) s += g_cpart[p * NN + j];
        g_c[j] = s;
    }
}

// ---------------- K4: out = relu((noradj @ (x*S)) @ Wfc + bfc), fused ----
// 512 threads = 16 i-rows x 32 f-threads (2 outputs each).
__global__ __launch_bounds__(512) void k_out(const float* __restrict__ x,
                                             const float* __restrict__ Wlin,
                                             const float* __restrict__ blin,
                                             const float* __restrict__ Wfc,
                                             const float* __restrict__ bfc,
                                             float* __restrict__ out) {
    const int iBase = blockIdx.x * 16;
    const int b = blockIdx.y;
    const int t = threadIdx.x;
    const int il = t >> 5;            // 0..15 row
    const int f2 = (t & 31) * 2;      // f offset (2 floats)

    __shared__ float sxs[32][64];
    __shared__ float nrs[32][17];
    __shared__ float wfcs[64 * 64];
    __shared__ float tmp[16][66];
    __shared__ float Ts[HH * NN];
    __shared__ float cs[NN];
    __shared__ float wlins[HH][64];
    __shared__ float blins[64];

    #pragma unroll
    for (int i = 0; i < 2; i++) ((float4*)wfcs)[t + i * 512] = ((const float4*)Wfc)[t + i * 512];
    ((float4*)Ts)[t] = ((const float4*)(g_T + b * HH * NN))[t];
    if (t < 128) ((float4*)cs)[t] = ((const float4*)g_c)[t];
    if (t < 64)  ((float4*)wlins)[t] = ((const float4*)Wlin)[t];
    if (t < 16)  ((float4*)blins)[t] = ((const float4*)blin)[t];
    __syncthreads();

    unsigned long long acc = 0ull;
    for (int j0 = 0; j0 < NN; j0 += 32) {
        {
            int jj = t >> 4, f4 = (t & 15) * 4;
            int jg = j0 + jj;
            float4 xv = *(const float4*)(x + ((b * NN) + jg) * FF + f4);
            float4 bl = *(const float4*)&blins[f4];
            float cj = cs[jg];
            float4 s4;
            s4.x = cj * bl.x; s4.y = cj * bl.y; s4.z = cj * bl.z; s4.w = cj * bl.w;
            #pragma unroll
            for (int hh = 0; hh < HH; hh++) {
                float tv = Ts[hh * NN + jg];
                float4 wl = *(const float4*)&wlins[hh][f4];
                s4.x += tv * wl.x; s4.y += tv * wl.y; s4.z += tv * wl.z; s4.w += tv * wl.w;
            }
            *(float4*)&sxs[jj][f4] =
                make_float4(xv.x * s4.x, xv.y * s4.y, xv.z * s4.z, xv.w * s4.w);
            int ii = t >> 5, jjn = t & 31;
            nrs[jjn][ii] = g_nor[(iBase + ii) * NN + j0 + jjn];
        }
        __syncthreads();
        #pragma unroll
        for (int jj = 0; jj < 32; jj++) {
            float nrv = nrs[jj][il];
            f2fma(acc, f2pack(nrv, nrv), *(const unsigned long long*)&sxs[jj][f2]);
        }
        __syncthreads();
    }

    float v0, v1;
    f2unpack(acc, v0, v1);
    tmp[il][f2] = v0; tmp[il][f2 + 1] = v1;
    __syncthreads();

    unsigned long long o0 = f2pack(bfc[f2], bfc[f2 + 1]);
    #pragma unroll
    for (int ff = 0; ff < 64; ff++) {
        float tv = tmp[il][ff];
        f2fma(o0, f2pack(tv, tv), *(const unsigned long long*)&wfcs[ff * 64 + f2]);
    }
    float r0, r1;
    f2unpack(o0, r0, r1);
    *(float2*)&out[((b * NN) + iBase + il) * FF + f2] =
        make_float2(fmaxf(r0, 0.f), fmaxf(r1, 0.f));
}

// ---------------- launch ----------------
extern "C" void kernel_launch(void* const* d_in, const int* in_sizes, int n_in,
                              void* d_out, int out_size) {
    const float* x    = (const float*)d_in[0];
    const float* adj  = (const float*)d_in[1];
    const float* Wq   = (const float*)d_in[2];
    const float* bq   = (const float*)d_in[3];
    const float* Wk   = (const float*)d_in[4];
    const float* bk   = (const float*)d_in[5];
    const float* Wlin = (const float*)d_in[6];
    const float* blin = (const float*)d_in[7];
    const float* Wfc  = (const float*)d_in[8];
    const float* bfc  = (const float*)d_in[9];
    float* out = (float*)d_out;

    static int attr_set = 0;
    if (!attr_set) {
        cudaFuncSetAttribute(k_attn_mma,
                             cudaFuncAttributeMaxDynamicSharedMemorySize, ATTN_DSM);
        attr_set = 1;
    }

    k_deg<<<NN, 256>>>(adj);
    k_nor<<<128, 512>>>(adj);
    k_proj<<<dim3(32, 8), 256>>>(x, Wq, bq, Wk, bk);
    k_attn_mma<<<dim3(8, HH, BB), 512, ATTN_DSM>>>();
    k_red<<<17, 512>>>();
    k_out<<<dim3(32, BB), 512>>>(x, Wlin, blin, Wfc, bfc, out);
}